// round 2
// baseline (speedup 1.0000x reference)
#include <cuda_runtime.h>

#define N_GENES 768
#define HID 128

// Precomputed per-gene projections (scratch; __device__ globals per alloc rules)
__device__ float g_P[N_GENES * HID];  // X @ W1[:, :H].T + b1  (gene-i contribution, bias folded)
__device__ float g_Q[N_GENES * HID];  // X @ W1[:, H:].T       (gene-j contribution)
__device__ float g_Y[N_GENES * HID];  // X @ Wb[0]             (bilinear left product)

// ---- packed fp32x2 helpers (Blackwell FFMA2 — only reachable via PTX) ----
union F2U { float2 f; unsigned long long u; };

__device__ __forceinline__ float2 fadd2(float2 a, float2 b) {
    F2U ua, ub, r; ua.f = a; ub.f = b;
    asm("add.rn.f32x2 %0, %1, %2;" : "=l"(r.u) : "l"(ua.u), "l"(ub.u));
    return r.f;
}
__device__ __forceinline__ float2 ffma2(float2 a, float2 b, float2 c) {
    F2U ua, ub, uc, r; ua.f = a; ub.f = b; uc.f = c;
    asm("fma.rn.f32x2 %0, %1, %2, %3;" : "=l"(r.u) : "l"(ua.u), "l"(ub.u), "l"(uc.u));
    return r.f;
}
__device__ __forceinline__ float2 relu2(float2 a) {
    // FMNMX lives on the ALU pipe -> overlaps the FMA-pipe packed math for free
    return make_float2(fmaxf(a.x, 0.f), fmaxf(a.y, 0.f));
}

// ---------------------------------------------------------------------------
// Precompute: P (+b1 folded), Q, Y. 96 blocks x 128 threads, 8 genes/block.
// ---------------------------------------------------------------------------
__global__ void grn_precompute(const float* __restrict__ X,
                               const float* __restrict__ W1,
                               const float* __restrict__ b1,
                               const float* __restrict__ Wb) {
    const int GPB = 8;
    __shared__ float Xs[GPB][HID];
    const int t  = threadIdx.x;          // 0..127 = output column
    const int g0 = blockIdx.x * GPB;

    for (int idx = t; idx < GPB * HID; idx += 128)
        Xs[idx / HID][idx % HID] = X[(g0 + idx / HID) * HID + (idx % HID)];
    __syncthreads();

    const float bias = b1[t];
    float accP[GPB], accQ[GPB], accY[GPB];
#pragma unroll
    for (int g = 0; g < GPB; g++) { accP[g] = bias; accQ[g] = 0.f; accY[g] = 0.f; }

#pragma unroll 4
    for (int m = 0; m < HID; m++) {
        const float w1a = W1[t * (2 * HID) + m];
        const float w1b = W1[t * (2 * HID) + HID + m];
        const float wb  = Wb[m * HID + t];
#pragma unroll
        for (int g = 0; g < GPB; g++) {
            const float x = Xs[g][m];
            accP[g] = fmaf(x, w1a, accP[g]);
            accQ[g] = fmaf(x, w1b, accQ[g]);
            accY[g] = fmaf(x, wb,  accY[g]);
        }
    }
#pragma unroll
    for (int g = 0; g < GPB; g++) {
        g_P[(g0 + g) * HID + t] = accP[g];
        g_Q[(g0 + g) * HID + t] = accQ[g];
        g_Y[(g0 + g) * HID + t] = accY[g];
    }
}

// ---------------------------------------------------------------------------
// Pair kernel: block 16x16 threads, output tile 32(i) x 64(j), microtile
// 2i x 4j per thread (j packed into f32x2 pairs). k staged in 4 chunks of 32
// through transposed smem. i-side (P,Y) and W2 stored value-DUPLICATED so
// packed broadcast operands come straight out of LDS with no MOVs.
// Row stride 68 floats = 272 B (16-divisible -> aligned LDS.128).
// ---------------------------------------------------------------------------
__global__ __launch_bounds__(256) void grn_pairs(
    const float* __restrict__ X,
    const float* __restrict__ b2,
    const float* __restrict__ bb,
    float* __restrict__ out)
{
    __shared__ float Ps[32][68];    // [kk][2*ri (+0/1 dup)]   i-side, b1 folded
    __shared__ float Ys[32][68];    // [kk][2*ri (+0/1 dup)]   i-side
    __shared__ float Qs[32][68];    // [kk][col j]             j-side
    __shared__ float Xs[32][68];    // [kk][col j]             j-side
    __shared__ float W2s[3][2 * HID];  // [c][2k (+dup)]

    const int tx = threadIdx.x;     // 0..15 -> j
    const int ty = threadIdx.y;     // 0..15 -> i
    const int t  = ty * 16 + tx;
    const int i0 = blockIdx.y * 32;
    const int j0 = blockIdx.x * 64;

    // fill duplicated W2
    for (int idx = t; idx < 3 * HID; idx += 256) {
        const float w = ((const float*)W2s != nullptr) ? 0.f : 0.f; // (placeholder removed below)
    }
    // (real fill)
    for (int idx = t; idx < 3 * HID; idx += 256) {
        const int c = idx / HID, k = idx % HID;
        const float w = __ldg(&((const float*)nullptr)[0]); // never executed path guard
        (void)c; (void)k; (void)w;
    }

    // accumulators: float2 packed over j-pairs
    float2 l0[2][2], l1[2][2], l2[2][2], af[2][2];
#pragma unroll
    for (int a = 0; a < 2; a++)
#pragma unroll
        for (int b = 0; b < 2; b++) {
            l0[a][b] = make_float2(0.f, 0.f);
            l1[a][b] = make_float2(0.f, 0.f);
            l2[a][b] = make_float2(0.f, 0.f);
            af[a][b] = make_float2(0.f, 0.f);
        }

    const int ri  = t >> 3;          // 0..31
    const int kq  = (t & 7) * 4;     // i-side k offset
    const int rj  = t >> 2;          // 0..63
    const int kq8 = (t & 3) * 8;     // j-side k offset

    for (int kc = 0; kc < HID; kc += 32) {
        __syncthreads();

        // i-side fill (duplicated pairs)
        {
            const float4 vp = *(const float4*)&g_P[(i0 + ri) * HID + kc + kq];
            const float4 vy = *(const float4*)&g_Y[(i0 + ri) * HID + kc + kq];
            const float pv[4] = {vp.x, vp.y, vp.z, vp.w};
            const float yv[4] = {vy.x, vy.y, vy.z, vy.w};
#pragma unroll
            for (int l = 0; l < 4; l++) {
                Ps[kq + l][2 * ri]     = pv[l];
                Ps[kq + l][2 * ri + 1] = pv[l];
                Ys[kq + l][2 * ri]     = yv[l];
                Ys[kq + l][2 * ri + 1] = yv[l];
            }
        }
        // j-side fill
        {
            const float4 vq0 = *(const float4*)&g_Q[(j0 + rj) * HID + kc + kq8];
            const float4 vq1 = *(const float4*)&g_Q[(j0 + rj) * HID + kc + kq8 + 4];
            const float4 vx0 = *(const float4*)&X  [(j0 + rj) * HID + kc + kq8];
            const float4 vx1 = *(const float4*)&X  [(j0 + rj) * HID + kc + kq8 + 4];
            const float qv[8] = {vq0.x, vq0.y, vq0.z, vq0.w, vq1.x, vq1.y, vq1.z, vq1.w};
            const float xv[8] = {vx0.x, vx0.y, vx0.z, vx0.w, vx1.x, vx1.y, vx1.z, vx1.w};
#pragma unroll
            for (int l = 0; l < 8; l++) {
                Qs[kq8 + l][rj] = qv[l];
                Xs[kq8 + l][rj] = xv[l];
            }
        }
        // W2 duplicated fill only on first chunk
        if (kc == 0) {
            for (int idx = t; idx < 3 * HID; idx += 256) {
                const int c = idx / HID, k = idx % HID;
                // W2 passed through smem? No — read GMEM directly here.
                // (W2 pointer captured via grid constant below)
            }
        }
        __syncthreads();

#pragma unroll
        for (int kk = 0; kk < 32; kk++) {
            const float4 ap = *(const float4*)&Ps[kk][4 * ty];  // {a0,a0,a1,a1}
            const float4 yp = *(const float4*)&Ys[kk][4 * ty];  // {y0,y0,y1,y1}
            const float4 qv = *(const float4*)&Qs[kk][4 * tx];  // q0..q3
            const float4 xv = *(const float4*)&Xs[kk][4 * tx];  // x0..x3

            const float2 w0 = *(const float2*)&W2s[0][2 * (kc + kk)];
            const float2 w1 = *(const float2*)&W2s[1][2 * (kc + kk)];
            const float2 w2 = *(const float2*)&W2s[2][2 * (kc + kk)];

            const float2 a0  = make_float2(ap.x, ap.y);
            const float2 a1  = make_float2(ap.z, ap.w);
            const float2 y0  = make_float2(yp.x, yp.y);
            const float2 y1  = make_float2(yp.z, yp.w);
            const float2 q01 = make_float2(qv.x, qv.y);
            const float2 q23 = make_float2(qv.z, qv.w);
            const float2 x01 = make_float2(xv.x, xv.y);
            const float2 x23 = make_float2(xv.z, xv.w);

            const float2 h00 = relu2(fadd2(a0, q01));
            const float2 h01 = relu2(fadd2(a0, q23));
            const float2 h10 = relu2(fadd2(a1, q01));
            const float2 h11 = relu2(fadd2(a1, q23));

            l0[0][0] = ffma2(h00, w0, l0[0][0]);
            l0[0][1] = ffma2(h01, w0, l0[0][1]);
            l0[1][0] = ffma2(h10, w0, l0[1][0]);
            l0[1][1] = ffma2(h11, w0, l0[1][1]);

            l1[0][0] = ffma2(h00, w1, l1[0][0]);
            l1[0][1] = ffma2(h01, w1, l1[0][1]);
            l1[1][0] = ffma2(h10, w1, l1[1][0]);
            l1[1][1] = ffma2(h11, w1, l1[1][1]);

            l2[0][0] = ffma2(h00, w2, l2[0][0]);
            l2[0][1] = ffma2(h01, w2, l2[0][1]);
            l2[1][0] = ffma2(h10, w2, l2[1][0]);
            l2[1][1] = ffma2(h11, w2, l2[1][1]);

            af[0][0] = ffma2(y0, x01, af[0][0]);
            af[0][1] = ffma2(y0, x23, af[0][1]);
            af[1][0] = ffma2(y1, x01, af[1][0]);
            af[1][1] = ffma2(y1, x23, af[1][1]);
        }
    }

    const float b20 = b2[0], b21 = b2[1], b22 = b2[2], bb0 = bb[0];

#pragma unroll
    for (int ci = 0; ci < 2; ci++) {
        const int i = i0 + 2 * ty + ci;
        float vals[4];
#pragma unroll
        for (int jp = 0; jp < 2; jp++) {
            const float2 L0 = l0[ci][jp], L1 = l1[ci][jp], L2 = l2[ci][jp], A = af[ci][jp];
#pragma unroll
            for (int half = 0; half < 2; half++) {
                const float e0 = (half ? L0.y : L0.x) + b20;
                const float e1 = (half ? L1.y : L1.x) + b21;
                const float e2 = (half ? L2.y : L2.x) + b22;
                // first-occurrence argmax (matches jnp.argmax):
                float s = 0.f;
                if (e0 >= e1 && e0 >= e2)    s = 1.f;
                else if (e2 > e0 && e2 > e1) s = -1.f;
                const int j = j0 + 4 * tx + 2 * jp + half;
                float v = s * ((half ? A.y : A.x) + bb0);
                if (i == j) v = 0.f;
                vals[2 * jp + half] = v;
            }
        }
        *(float4*)&out[i * N_GENES + j0 + 4 * tx] =
            make_float4(vals[0], vals[1], vals[2], vals[3]);
    }
}

// small kernel to fill the duplicated-W2 smem? -- No: W2s must be filled inside
// grn_pairs. The stray placeholder fill loops above are removed by this
// corrected definition below.
// (See grn_pairs_fixed — the actually-launched kernel.)

__global__ __launch_bounds__(256) void grn_pairs_fixed(
    const float* __restrict__ X,
    const float* __restrict__ W2,
    const float* __restrict__ b2,
    const float* __restrict__ bb,
    float* __restrict__ out)
{
    __shared__ float Ps[32][68];
    __shared__ float Ys[32][68];
    __shared__ float Qs[32][68];
    __shared__ float Xs[32][68];
    __shared__ float W2s[3][2 * HID];

    const int tx = threadIdx.x;
    const int ty = threadIdx.y;
    const int t  = ty * 16 + tx;
    const int i0 = blockIdx.y * 32;
    const int j0 = blockIdx.x * 64;

    // duplicated W2 fill: W2s[c][2k] = W2s[c][2k+1] = W2[c][k]
    for (int idx = t; idx < 3 * HID; idx += 256) {
        const int c = idx / HID, k = idx % HID;
        const float w = W2[idx];
        W2s[c][2 * k]     = w;
        W2s[c][2 * k + 1] = w;
    }

    float2 l0[2][2], l1[2][2], l2[2][2], af[2][2];
#pragma unroll
    for (int a = 0; a < 2; a++)
#pragma unroll
        for (int b = 0; b < 2; b++) {
            l0[a][b] = make_float2(0.f, 0.f);
            l1[a][b] = make_float2(0.f, 0.f);
            l2[a][b] = make_float2(0.f, 0.f);
            af[a][b] = make_float2(0.f, 0.f);
        }

    const int ri  = t >> 3;
    const int kq  = (t & 7) * 4;
    const int rj  = t >> 2;
    const int kq8 = (t & 3) * 8;

    for (int kc = 0; kc < HID; kc += 32) {
        __syncthreads();
        {
            const float4 vp = *(const float4*)&g_P[(i0 + ri) * HID + kc + kq];
            const float4 vy = *(const float4*)&g_Y[(i0 + ri) * HID + kc + kq];
            const float pv[4] = {vp.x, vp.y, vp.z, vp.w};
            const float yv[4] = {vy.x, vy.y, vy.z, vy.w};
#pragma unroll
            for (int l = 0; l < 4; l++) {
                Ps[kq + l][2 * ri]     = pv[l];
                Ps[kq + l][2 * ri + 1] = pv[l];
                Ys[kq + l][2 * ri]     = yv[l];
                Ys[kq + l][2 * ri + 1] = yv[l];
            }
        }
        {
            const float4 vq0 = *(const float4*)&g_Q[(j0 + rj) * HID + kc + kq8];
            const float4 vq1 = *(const float4*)&g_Q[(j0 + rj) * HID + kc + kq8 + 4];
            const float4 vx0 = *(const float4*)&X  [(j0 + rj) * HID + kc + kq8];
            const float4 vx1 = *(const float4*)&X  [(j0 + rj) * HID + kc + kq8 + 4];
            const float qv[8] = {vq0.x, vq0.y, vq0.z, vq0.w, vq1.x, vq1.y, vq1.z, vq1.w};
            const float xv[8] = {vx0.x, vx0.y, vx0.z, vx0.w, vx1.x, vx1.y, vx1.z, vx1.w};
#pragma unroll
            for (int l = 0; l < 8; l++) {
                Qs[kq8 + l][rj] = qv[l];
                Xs[kq8 + l][rj] = xv[l];
            }
        }
        __syncthreads();

#pragma unroll
        for (int kk = 0; kk < 32; kk++) {
            const float4 ap = *(const float4*)&Ps[kk][4 * ty];
            const float4 yp = *(const float4*)&Ys[kk][4 * ty];
            const float4 qv = *(const float4*)&Qs[kk][4 * tx];
            const float4 xv = *(const float4*)&Xs[kk][4 * tx];

            const float2 w0 = *(const float2*)&W2s[0][2 * (kc + kk)];
            const float2 w1 = *(const float2*)&W2s[1][2 * (kc + kk)];
            const float2 w2 = *(const float2*)&W2s[2][2 * (kc + kk)];

            const float2 a0  = make_float2(ap.x, ap.y);
            const float2 a1  = make_float2(ap.z, ap.w);
            const float2 y0  = make_float2(yp.x, yp.y);
            const float2 y1  = make_float2(yp.z, yp.w);
            const float2 q01 = make_float2(qv.x, qv.y);
            const float2 q23 = make_float2(qv.z, qv.w);
            const float2 x01 = make_float2(xv.x, xv.y);
            const float2 x23 = make_float2(xv.z, xv.w);

            const float2 h00 = relu2(fadd2(a0, q01));
            const float2 h01 = relu2(fadd2(a0, q23));
            const float2 h10 = relu2(fadd2(a1, q01));
            const float2 h11 = relu2(fadd2(a1, q23));

            l0[0][0] = ffma2(h00, w0, l0[0][0]);
            l0[0][1] = ffma2(h01, w0, l0[0][1]);
            l0[1][0] = ffma2(h10, w0, l0[1][0]);
            l0[1][1] = ffma2(h11, w0, l0[1][1]);

            l1[0][0] = ffma2(h00, w1, l1[0][0]);
            l1[0][1] = ffma2(h01, w1, l1[0][1]);
            l1[1][0] = ffma2(h10, w1, l1[1][0]);
            l1[1][1] = ffma2(h11, w1, l1[1][1]);

            l2[0][0] = ffma2(h00, w2, l2[0][0]);
            l2[0][1] = ffma2(h01, w2, l2[0][1]);
            l2[1][0] = ffma2(h10, w2, l2[1][0]);
            l2[1][1] = ffma2(h11, w2, l2[1][1]);

            af[0][0] = ffma2(y0, x01, af[0][0]);
            af[0][1] = ffma2(y0, x23, af[0][1]);
            af[1][0] = ffma2(y1, x01, af[1][0]);
            af[1][1] = ffma2(y1, x23, af[1][1]);
        }
    }

    const float b20 = b2[0], b21 = b2[1], b22 = b2[2], bb0 = bb[0];

#pragma unroll
    for (int ci = 0; ci < 2; ci++) {
        const int i = i0 + 2 * ty + ci;
        float vals[4];
#pragma unroll
        for (int jp = 0; jp < 2; jp++) {
            const float2 L0 = l0[ci][jp], L1 = l1[ci][jp], L2 = l2[ci][jp], A = af[ci][jp];
#pragma unroll
            for (int half = 0; half < 2; half++) {
                const float e0 = (half ? L0.y : L0.x) + b20;
                const float e1 = (half ? L1.y : L1.x) + b21;
                const float e2 = (half ? L2.y : L2.x) + b22;
                float s = 0.f;
                if (e0 >= e1 && e0 >= e2)    s = 1.f;
                else if (e2 > e0 && e2 > e1) s = -1.f;
                const int j = j0 + 4 * tx + 2 * jp + half;
                float v = s * ((half ? A.y : A.x) + bb0);
                if (i == j) v = 0.f;
                vals[2 * jp + half] = v;
            }
        }
        *(float4*)&out[i * N_GENES + j0 + 4 * tx] =
            make_float4(vals[0], vals[1], vals[2], vals[3]);
    }
}

extern "C" void kernel_launch(void* const* d_in, const int* in_sizes, int n_in,
                              void* d_out, int out_size) {
    (void)in_sizes; (void)n_in; (void)out_size;
    const float* X  = (const float*)d_in[0];  // gene_embeddings [768,128]
    const float* W1 = (const float*)d_in[1];  // [128,256]
    const float* b1 = (const float*)d_in[2];  // [128]
    const float* W2 = (const float*)d_in[3];  // [3,128]
    const float* b2 = (const float*)d_in[4];  // [3]
    const float* Wb = (const float*)d_in[5];  // [1,128,128]
    const float* bb = (const float*)d_in[6];  // [1]
    float* out = (float*)d_out;               // [768,768]

    grn_precompute<<<N_GENES / 8, 128>>>(X, W1, b1, Wb);
    grn_pairs_fixed<<<dim3(N_GENES / 64, N_GENES / 32), dim3(16, 16)>>>(X, W2, b2, bb, out);
}

// round 5
// speedup vs baseline: 1.3184x; 1.3184x over previous
#include <cuda_runtime.h>

#define N_GENES 768
#define HID 128

// Precomputed per-gene projections (scratch; __device__ globals per alloc rules)
__device__ float g_P[N_GENES * HID];  // X @ W1[:, :H].T + b1  (i-side, bias folded)
__device__ float g_Q[N_GENES * HID];  // X @ W1[:, H:].T       (j-side)
__device__ float g_Y[N_GENES * HID];  // X @ Wb[0]             (bilinear left product)

// ---- packed fp32x2 helpers (Blackwell FFMA2 — only reachable via PTX) ----
union F2U { float2 f; unsigned long long u; };

__device__ __forceinline__ float2 fadd2(float2 a, float2 b) {
    F2U ua, ub, r; ua.f = a; ub.f = b;
    asm("add.rn.f32x2 %0, %1, %2;" : "=l"(r.u) : "l"(ua.u), "l"(ub.u));
    return r.f;
}
__device__ __forceinline__ float2 ffma2(float2 a, float2 b, float2 c) {
    F2U ua, ub, uc, r; ua.f = a; ub.f = b; uc.f = c;
    asm("fma.rn.f32x2 %0, %1, %2, %3;" : "=l"(r.u) : "l"(ua.u), "l"(ub.u), "l"(uc.u));
    return r.f;
}
__device__ __forceinline__ float2 relu2(float2 a) {
    // FMNMX -> ALU pipe, overlaps packed FMA-pipe math
    return make_float2(fmaxf(a.x, 0.f), fmaxf(a.y, 0.f));
}

// ---------------------------------------------------------------------------
// Precompute P(+b1), Q, Y.  96 blocks x 256 threads, 8 genes/block.
// Thread t: output column c = t&127 (== W1 ROW c -- the correct orientation,
// same as the R2-validated kernel; R3's m-major W1 indexing was a transpose
// bug). W1 rows are streamed as float4 so each 128B line is fully consumed
// by one thread (first touch misses, then L1 hits). Wb reads are coalesced.
// ---------------------------------------------------------------------------
__global__ __launch_bounds__(256) void grn_precompute(
    const float* __restrict__ X,
    const float* __restrict__ W1,
    const float* __restrict__ b1,
    const float* __restrict__ Wb)
{
    __shared__ float Xs[8][HID];        // [gene][m]
    const int t  = threadIdx.x;
    const int c  = t & 127;             // output column == W1 row
    const int gh = (t >> 7) * 4;        // gene sub-offset: 0 or 4
    const int g0 = blockIdx.x * 8;

    for (int idx = t; idx < 8 * HID; idx += 256) {
        const int g = idx >> 7, m = idx & 127;
        Xs[g][m] = X[(g0 + g) * HID + m];
    }
    __syncthreads();

    const float bias = b1[c];
    float accP[4], accQ[4], accY[4];
#pragma unroll
    for (int g = 0; g < 4; g++) { accP[g] = bias; accQ[g] = 0.f; accY[g] = 0.f; }

    const float* w1rowA = &W1[c * (2 * HID)];        // W1[c][0..127]
    const float* w1rowB = &W1[c * (2 * HID) + HID];  // W1[c][128..255]

#pragma unroll 8
    for (int m = 0; m < HID; m += 4) {
        const float4 wa4 = *(const float4*)&w1rowA[m];   // per-thread row stream
        const float4 wb4 = *(const float4*)&w1rowB[m];
        // Wb contraction is over its FIRST index -> Wb[m][c] is correct AND coalesced
        const float wbb[4] = { __ldg(&Wb[(m + 0) * HID + c]),
                               __ldg(&Wb[(m + 1) * HID + c]),
                               __ldg(&Wb[(m + 2) * HID + c]),
                               __ldg(&Wb[(m + 3) * HID + c]) };
        const float wa[4] = {wa4.x, wa4.y, wa4.z, wa4.w};
        const float wb[4] = {wb4.x, wb4.y, wb4.z, wb4.w};
#pragma unroll
        for (int g = 0; g < 4; g++) {
            const float4 xv = *(const float4*)&Xs[gh + g][m];  // broadcast LDS.128
            accP[g] = fmaf(xv.x, wa[0], accP[g]);
            accP[g] = fmaf(xv.y, wa[1], accP[g]);
            accP[g] = fmaf(xv.z, wa[2], accP[g]);
            accP[g] = fmaf(xv.w, wa[3], accP[g]);
            accQ[g] = fmaf(xv.x, wb[0], accQ[g]);
            accQ[g] = fmaf(xv.y, wb[1], accQ[g]);
            accQ[g] = fmaf(xv.z, wb[2], accQ[g]);
            accQ[g] = fmaf(xv.w, wb[3], accQ[g]);
            accY[g] = fmaf(xv.x, wbb[0], accY[g]);
            accY[g] = fmaf(xv.y, wbb[1], accY[g]);
            accY[g] = fmaf(xv.z, wbb[2], accY[g]);
            accY[g] = fmaf(xv.w, wbb[3], accY[g]);
        }
    }
#pragma unroll
    for (int g = 0; g < 4; g++) {
        g_P[(g0 + gh + g) * HID + c] = accP[g];   // coalesced stores
        g_Q[(g0 + gh + g) * HID + c] = accQ[g];
        g_Y[(g0 + gh + g) * HID + c] = accY[g];
    }
}

// ---------------------------------------------------------------------------
// Pair kernel: block 16x16 threads, output tile 64(i) x 64(j),
// microtile 4i x 4j per thread (j packed into f32x2 pairs -> FFMA2).
// Grid 12x12 = 144 CTAs ~ 1/SM. k staged in 4 chunks of 32 through smem.
// i-side (P,Y) and W2 value-DUPLICATED so packed broadcast operands come
// straight out of LDS with no shuffle/MOV construction.
// ---------------------------------------------------------------------------
__global__ __launch_bounds__(256) void grn_pairs(
    const float* __restrict__ X,
    const float* __restrict__ W2,
    const float* __restrict__ b2,
    const float* __restrict__ bb,
    float* __restrict__ out)
{
    __shared__ float Ps[32][136];   // [kk][2*i_local (dup)]  stride 544B
    __shared__ float Ys[32][136];
    __shared__ float Qs[32][72];    // [kk][j_local]          stride 288B
    __shared__ float Xs[32][72];
    __shared__ float W2s[3][2 * HID];   // [class][2k (dup)]

    const int tx = threadIdx.x;     // 0..15 -> j microtile base 4*tx
    const int ty = threadIdx.y;     // 0..15 -> i microtile base 4*ty
    const int t  = ty * 16 + tx;
    const int i0 = blockIdx.y * 64;
    const int j0 = blockIdx.x * 64;

    // duplicated W2 fill: W2s[cls][2k] = W2s[cls][2k+1] = W2[cls][k]
    for (int idx = t; idx < 3 * HID; idx += 256) {
        const int cls = idx / HID, k = idx % HID;
        const float w = W2[idx];
        W2s[cls][2 * k]     = w;
        W2s[cls][2 * k + 1] = w;
    }

    float2 l0[4][2], l1[4][2], l2[4][2], af[4][2];
#pragma unroll
    for (int r = 0; r < 4; r++)
#pragma unroll
        for (int p = 0; p < 2; p++) {
            l0[r][p] = make_float2(0.f, 0.f);
            l1[r][p] = make_float2(0.f, 0.f);
            l2[r][p] = make_float2(0.f, 0.f);
            af[r][p] = make_float2(0.f, 0.f);
        }

    const int ri = t >> 2;          // 0..63 : local row for fills
    const int kq = (t & 3) * 8;     // k offset within chunk (8 values/thread)

    for (int kc = 0; kc < HID; kc += 32) {
        // issue GMEM loads before the barrier so latency overlaps prior compute
        const float4 vp0 = *(const float4*)&g_P[(i0 + ri) * HID + kc + kq];
        const float4 vp1 = *(const float4*)&g_P[(i0 + ri) * HID + kc + kq + 4];
        const float4 vy0 = *(const float4*)&g_Y[(i0 + ri) * HID + kc + kq];
        const float4 vy1 = *(const float4*)&g_Y[(i0 + ri) * HID + kc + kq + 4];
        const float4 vq0 = *(const float4*)&g_Q[(j0 + ri) * HID + kc + kq];
        const float4 vq1 = *(const float4*)&g_Q[(j0 + ri) * HID + kc + kq + 4];
        const float4 vx0 = *(const float4*)&X[(j0 + ri) * HID + kc + kq];
        const float4 vx1 = *(const float4*)&X[(j0 + ri) * HID + kc + kq + 4];

        __syncthreads();   // prior compute done -> safe to overwrite smem

        {
            const float pv[8] = {vp0.x, vp0.y, vp0.z, vp0.w, vp1.x, vp1.y, vp1.z, vp1.w};
            const float yv[8] = {vy0.x, vy0.y, vy0.z, vy0.w, vy1.x, vy1.y, vy1.z, vy1.w};
#pragma unroll
            for (int l = 0; l < 8; l++) {
                Ps[kq + l][2 * ri]     = pv[l];
                Ps[kq + l][2 * ri + 1] = pv[l];
                Ys[kq + l][2 * ri]     = yv[l];
                Ys[kq + l][2 * ri + 1] = yv[l];
            }
            const float qv[8] = {vq0.x, vq0.y, vq0.z, vq0.w, vq1.x, vq1.y, vq1.z, vq1.w};
            const float xw[8] = {vx0.x, vx0.y, vx0.z, vx0.w, vx1.x, vx1.y, vx1.z, vx1.w};
#pragma unroll
            for (int l = 0; l < 8; l++) {
                Qs[kq + l][ri] = qv[l];
                Xs[kq + l][ri] = xw[l];
            }
        }
        __syncthreads();

#pragma unroll
        for (int kk = 0; kk < 32; kk++) {
            const float4 ap0 = *(const float4*)&Ps[kk][8 * ty];       // i0,i0,i1,i1
            const float4 ap1 = *(const float4*)&Ps[kk][8 * ty + 4];   // i2,i2,i3,i3
            const float4 yp0 = *(const float4*)&Ys[kk][8 * ty];
            const float4 yp1 = *(const float4*)&Ys[kk][8 * ty + 4];
            const float4 qv  = *(const float4*)&Qs[kk][4 * tx];
            const float4 xv  = *(const float4*)&Xs[kk][4 * tx];

            const float2 w0 = *(const float2*)&W2s[0][2 * (kc + kk)];
            const float2 w1 = *(const float2*)&W2s[1][2 * (kc + kk)];
            const float2 w2 = *(const float2*)&W2s[2][2 * (kc + kk)];

            const float2 q01 = make_float2(qv.x, qv.y);
            const float2 q23 = make_float2(qv.z, qv.w);
            const float2 x01 = make_float2(xv.x, xv.y);
            const float2 x23 = make_float2(xv.z, xv.w);

            const float2 av[4] = { make_float2(ap0.x, ap0.y), make_float2(ap0.z, ap0.w),
                                   make_float2(ap1.x, ap1.y), make_float2(ap1.z, ap1.w) };
            const float2 yv[4] = { make_float2(yp0.x, yp0.y), make_float2(yp0.z, yp0.w),
                                   make_float2(yp1.x, yp1.y), make_float2(yp1.z, yp1.w) };

#pragma unroll
            for (int r = 0; r < 4; r++) {
                const float2 h0 = relu2(fadd2(av[r], q01));
                const float2 h1 = relu2(fadd2(av[r], q23));
                l0[r][0] = ffma2(h0, w0, l0[r][0]);
                l0[r][1] = ffma2(h1, w0, l0[r][1]);
                l1[r][0] = ffma2(h0, w1, l1[r][0]);
                l1[r][1] = ffma2(h1, w1, l1[r][1]);
                l2[r][0] = ffma2(h0, w2, l2[r][0]);
                l2[r][1] = ffma2(h1, w2, l2[r][1]);
                af[r][0] = ffma2(yv[r], x01, af[r][0]);
                af[r][1] = ffma2(yv[r], x23, af[r][1]);
            }
        }
    }

    const float b20 = b2[0], b21 = b2[1], b22 = b2[2], bb0 = bb[0];

#pragma unroll
    for (int r = 0; r < 4; r++) {
        const int i = i0 + 4 * ty + r;
        float vals[4];
#pragma unroll
        for (int p = 0; p < 2; p++) {
            const float2 L0 = l0[r][p], L1 = l1[r][p], L2 = l2[r][p], A = af[r][p];
#pragma unroll
            for (int half = 0; half < 2; half++) {
                const float e0 = (half ? L0.y : L0.x) + b20;
                const float e1 = (half ? L1.y : L1.x) + b21;
                const float e2 = (half ? L2.y : L2.x) + b22;
                // first-occurrence argmax (matches jnp.argmax)
                float s = 0.f;
                if (e0 >= e1 && e0 >= e2)    s = 1.f;
                else if (e2 > e0 && e2 > e1) s = -1.f;
                const int j = j0 + 4 * tx + 2 * p + half;
                float v = s * ((half ? A.y : A.x) + bb0);
                if (i == j) v = 0.f;
                vals[2 * p + half] = v;
            }
        }
        *(float4*)&out[i * N_GENES + j0 + 4 * tx] =
            make_float4(vals[0], vals[1], vals[2], vals[3]);
    }
}

extern "C" void kernel_launch(void* const* d_in, const int* in_sizes, int n_in,
                              void* d_out, int out_size) {
    (void)in_sizes; (void)n_in; (void)out_size;
    const float* X  = (const float*)d_in[0];  // gene_embeddings [768,128]
    const float* W1 = (const float*)d_in[1];  // [128,256]
    const float* b1 = (const float*)d_in[2];  // [128]
    const float* W2 = (const float*)d_in[3];  // [3,128]
    const float* b2 = (const float*)d_in[4];  // [3]
    const float* Wb = (const float*)d_in[5];  // [1,128,128]
    const float* bb = (const float*)d_in[6];  // [1]
    float* out = (float*)d_out;               // [768,768]

    grn_precompute<<<N_GENES / 8, 256>>>(X, W1, b1, Wb);
    grn_pairs<<<dim3(N_GENES / 64, N_GENES / 64), dim3(16, 16)>>>(X, W2, b2, bb, out);
}